// round 13
// baseline (speedup 1.0000x reference)
#include <cuda_runtime.h>
#include <cstdint>

#define UNITS   512
#define NBATCH  512
#define DIM     64
#define MT      64            // batch tile (double-buffered)
#define BPC     256           // batch rows per CTA (2 CTAs per unit)
#define NTILES  (BPC / MT)    // 4
#define NT      512
#define LD      68            // stride: bank(4g+t) all-distinct for fragment LDS
#define WSZ     (DIM * LD)    // 4352 floats per weight matrix
#define TSZ     (MT * LD)     // 4352 floats per activation tile buffer

// ---- smem float offsets (total 43776 floats = 175,104 B; proven envelope) ----
#define SW_OFF  0                     // 6*WSZ  tf32 weights TRANSPOSED [o][k], stride LD
#define SXB_OFF (6 * WSZ)             // 2*TSZ  raw x tile, double-buffered
#define SHB_OFF (SXB_OFF + 2 * TSZ)   // 2*TSZ  raw h tile, double-buffered
#define SB_OFF  (SHB_OFF + 2 * TSZ)   // 4*64 biases: r, z, in, hn
#define SMEM_FLOATS (SB_OFF + 256)

__device__ __forceinline__ uint32_t f2tf32(float x) {
    uint32_t u;
    asm volatile("cvt.rna.tf32.f32 %0, %1;" : "=r"(u) : "f"(x));
    return u;
}

__device__ __forceinline__ void mma8(float* d, const uint32_t* a, const uint32_t* b) {
    asm volatile(
        "mma.sync.aligned.m16n8k8.row.col.f32.tf32.tf32.f32 "
        "{%0,%1,%2,%3}, {%4,%5,%6,%7}, {%8,%9}, {%0,%1,%2,%3};"
        : "+f"(d[0]), "+f"(d[1]), "+f"(d[2]), "+f"(d[3])
        : "r"(a[0]), "r"(a[1]), "r"(a[2]), "r"(a[3]), "r"(b[0]), "r"(b[1]));
}

__device__ __forceinline__ float fast_sigmoid(float v) { return 1.f / (1.f + __expf(-v)); }
__device__ __forceinline__ float fast_tanh(float v)   { return 2.f / (1.f + __expf(-2.f * v)) - 1.f; }

// ---------------------------------------------------------------------------
// Grid = 1024: CTA (u, half) handles unit u, batch rows [half*256, half*256+256)
// as 4 cp.async double-buffered tiles of 64 rows. 512 threads = 16 warps
// (4 row-groups x 4 col-groups, warp tile 16x16). Weights resident in smem,
// transposed, conflict-free scalar fragment loads (all constructs R10-proven).
// A-fragments software-pipelined one k-step ahead of the MMAs.
// ---------------------------------------------------------------------------
__global__ void __launch_bounds__(NT, 1)
gru_mma_split_kernel(const float* __restrict__ x,  const float* __restrict__ h,
                     const float* __restrict__ Wir, const float* __restrict__ bir,
                     const float* __restrict__ Whr, const float* __restrict__ bhr,
                     const float* __restrict__ Wiz, const float* __restrict__ biz,
                     const float* __restrict__ Whz, const float* __restrict__ bhz,
                     const float* __restrict__ Win, const float* __restrict__ bin,
                     const float* __restrict__ Whn, const float* __restrict__ bhn,
                     float* __restrict__ out) {
    extern __shared__ float smem[];

    const int u     = blockIdx.x >> 1;
    const int bbase = (blockIdx.x & 1) * BPC;
    const int tid  = threadIdx.x;
    const int lane = tid & 31;
    const int wid  = tid >> 5;
    const int g    = lane >> 2;            // mma groupID (0..7)
    const int t    = lane & 3;             // thread-in-group
    const int rowBase = (wid & 3) << 4;    // 4 row-warps x 16 rows = 64
    const int colBase = (wid >> 2) << 4;   // 4 col-warps x 16 cols = 64

    const uint32_t sxb_u32 = (uint32_t)__cvta_generic_to_shared(smem + SXB_OFF);
    const uint32_t shb_u32 = (uint32_t)__cvta_generic_to_shared(smem + SHB_OFF);

    // prefetch tile 0 into buffer 0 (overlaps the weight prologue below)
    {
#pragma unroll
        for (int it = 0; it < 2; it++) {
            int cidx = tid + it * NT;
            int r  = cidx >> 4;
            int c4 = (cidx & 15) * 4;
            size_t ga = ((size_t)(bbase + r) * UNITS + u) * DIM + c4;
            uint32_t off = (uint32_t)(r * LD + c4) * 4;
            asm volatile("cp.async.cg.shared.global [%0], [%1], 16;"
                         :: "r"(sxb_u32 + off), "l"(x + ga));
            asm volatile("cp.async.cg.shared.global [%0], [%1], 16;"
                         :: "r"(shb_u32 + off), "l"(h + ga));
        }
        asm volatile("cp.async.commit_group;");
    }

    // ---- stage 6 weight matrices once, TRANSPOSED: W[k][o] -> sW[o*LD + k] ----
    {
        const float* wsrc[6] = {Wir, Whr, Wiz, Whz, Win, Whn};
        const size_t wOff = (size_t)u * DIM * DIM;
#pragma unroll
        for (int gg = 0; gg < 6; gg++) {
            const float* wp = wsrc[gg] + wOff;
            float* dst = smem + SW_OFF + gg * WSZ;
            for (int i = tid; i < DIM * DIM / 4; i += NT) {
                int k  = i >> 4;
                int o4 = (i & 15) * 4;
                float4 v = *reinterpret_cast<const float4*>(wp + k * DIM + o4);
                dst[(o4 + 0) * LD + k] = __uint_as_float(f2tf32(v.x));
                dst[(o4 + 1) * LD + k] = __uint_as_float(f2tf32(v.y));
                dst[(o4 + 2) * LD + k] = __uint_as_float(f2tf32(v.z));
                dst[(o4 + 3) * LD + k] = __uint_as_float(f2tf32(v.w));
            }
        }
        if (tid < DIM) {
            const size_t bo = (size_t)u * DIM + tid;
            smem[SB_OFF + tid]           = bir[bo] + bhr[bo];
            smem[SB_OFF + 64 + tid]      = biz[bo] + bhz[bo];
            smem[SB_OFF + 128 + tid]     = bin[bo];
            smem[SB_OFF + 192 + tid]     = bhn[bo];
        }
    }

    const float* sW = smem + SW_OFF;

    for (int tile = 0; tile < NTILES; tile++) {
        const int buf = tile & 1;
        const int b0  = bbase + tile * MT;

        asm volatile("cp.async.wait_group 0;" ::: "memory");
        __syncthreads();

        if (tile + 1 < NTILES) {
            const int b0n = b0 + MT;
            const uint32_t boff = (uint32_t)((buf ^ 1) * TSZ) * 4;
#pragma unroll
            for (int it = 0; it < 2; it++) {
                int cidx = tid + it * NT;
                int r  = cidx >> 4;
                int c4 = (cidx & 15) * 4;
                size_t ga = ((size_t)(b0n + r) * UNITS + u) * DIM + c4;
                uint32_t off = boff + (uint32_t)(r * LD + c4) * 4;
                asm volatile("cp.async.cg.shared.global [%0], [%1], 16;"
                             :: "r"(sxb_u32 + off), "l"(x + ga));
                asm volatile("cp.async.cg.shared.global [%0], [%1], 16;"
                             :: "r"(shb_u32 + off), "l"(h + ga));
            }
            asm volatile("cp.async.commit_group;");
        }

        const float* sXt = smem + SXB_OFF + buf * TSZ;
        const float* sHt = smem + SHB_OFF + buf * TSZ;

        // ---- fused 6-GEMM k-loop, A-fragments pipelined one k-step ahead ----
        float accR[8], accZ[8], accN[8], accH[8];
#pragma unroll
        for (int i = 0; i < 8; i++) {
            accR[i] = 0.f; accZ[i] = 0.f; accN[i] = 0.f; accH[i] = 0.f;
        }

        uint32_t ax[2][4], ah[2][4];
        {   // k-step 0 into buffer 0 (R10-proven addressing)
            const float* ap = sXt + (rowBase + g) * LD + t;
            ax[0][0] = f2tf32(ap[0]);
            ax[0][1] = f2tf32(ap[8 * LD]);
            ax[0][2] = f2tf32(ap[4]);
            ax[0][3] = f2tf32(ap[8 * LD + 4]);
            const float* hp = sHt + (rowBase + g) * LD + t;
            ah[0][0] = f2tf32(hp[0]);
            ah[0][1] = f2tf32(hp[8 * LD]);
            ah[0][2] = f2tf32(hp[4]);
            ah[0][3] = f2tf32(hp[8 * LD + 4]);
        }

#pragma unroll
        for (int ks = 0; ks < 8; ks++) {
            const int cur = ks & 1;
            const int nxt = cur ^ 1;
            if (ks < 7) {   // prefetch A-fragments for k-step ks+1
                const int k0 = (ks + 1) * 8;
                const float* ap = sXt + (rowBase + g) * LD + k0 + t;
                ax[nxt][0] = f2tf32(ap[0]);
                ax[nxt][1] = f2tf32(ap[8 * LD]);
                ax[nxt][2] = f2tf32(ap[4]);
                ax[nxt][3] = f2tf32(ap[8 * LD + 4]);
                const float* hp = sHt + (rowBase + g) * LD + k0 + t;
                ah[nxt][0] = f2tf32(hp[0]);
                ah[nxt][1] = f2tf32(hp[8 * LD]);
                ah[nxt][2] = f2tf32(hp[4]);
                ah[nxt][3] = f2tf32(hp[8 * LD + 4]);
            }
            const int k0c = ks * 8;
#pragma unroll
            for (int ni = 0; ni < 2; ni++) {
                const float* bp = sW + (colBase + ni * 8 + g) * LD + k0c + t;
                uint32_t b[6][2];
#pragma unroll
                for (int w = 0; w < 6; w++) {
                    b[w][0] = __float_as_uint(bp[w * WSZ]);
                    b[w][1] = __float_as_uint(bp[w * WSZ + 4]);
                }
                const int o = ni * 4;
                mma8(accR + o, ax[cur], b[0]);   // x@Wir
                mma8(accR + o, ah[cur], b[1]);   // h@Whr
                mma8(accZ + o, ax[cur], b[2]);   // x@Wiz
                mma8(accZ + o, ah[cur], b[3]);   // h@Whz
                mma8(accN + o, ax[cur], b[4]);   // x@Win
                mma8(accH + o, ah[cur], b[5]);   // h@Whn
            }
        }

        // ---- fused GRU epilogue, direct float2 gmem stores ----
#pragma unroll
        for (int ni = 0; ni < 2; ni++) {
            const int col = colBase + ni * 8 + 2 * t;
#pragma unroll
            for (int half = 0; half < 2; half++) {
                const int row = rowBase + g + half * 8;
                float2 hv = *reinterpret_cast<const float2*>(sHt + row * LD + col);
                float2 res;
                {
                    const int idx = ni * 4 + half * 2;
                    float r_ = fast_sigmoid(accR[idx] + smem[SB_OFF + col]);
                    float z_ = fast_sigmoid(accZ[idx] + smem[SB_OFF + 64 + col]);
                    float n_ = fast_tanh(accN[idx] + smem[SB_OFF + 128 + col] +
                                         r_ * (accH[idx] + smem[SB_OFF + 192 + col]));
                    res.x = (1.f - z_) * n_ + z_ * hv.x;
                }
                {
                    const int idx = ni * 4 + half * 2 + 1;
                    float r_ = fast_sigmoid(accR[idx] + smem[SB_OFF + col + 1]);
                    float z_ = fast_sigmoid(accZ[idx] + smem[SB_OFF + 64 + col + 1]);
                    float n_ = fast_tanh(accN[idx] + smem[SB_OFF + 128 + col + 1] +
                                         r_ * (accH[idx] + smem[SB_OFF + 192 + col + 1]));
                    res.y = (1.f - z_) * n_ + z_ * hv.y;
                }
                size_t ga = ((size_t)(b0 + row) * UNITS + u) * DIM + col;
                *reinterpret_cast<float2*>(out + ga) = res;
            }
        }
    }
}

// ---------------------------------------------------------------------------
extern "C" void kernel_launch(void* const* d_in, const int* in_sizes, int n_in,
                              void* d_out, int out_size) {
    (void)in_sizes; (void)n_in; (void)out_size;
    const float* x   = (const float*)d_in[0];
    const float* h   = (const float*)d_in[1];
    const float* Wir = (const float*)d_in[2];
    const float* bir = (const float*)d_in[3];
    const float* Whr = (const float*)d_in[4];
    const float* bhr = (const float*)d_in[5];
    const float* Wiz = (const float*)d_in[6];
    const float* biz = (const float*)d_in[7];
    const float* Whz = (const float*)d_in[8];
    const float* bhz = (const float*)d_in[9];
    const float* Win = (const float*)d_in[10];
    const float* bin = (const float*)d_in[11];
    const float* Whn = (const float*)d_in[12];
    const float* bhn = (const float*)d_in[13];
    float* out = (float*)d_out;

    const size_t smemBytes = (size_t)SMEM_FLOATS * sizeof(float);
    cudaFuncSetAttribute(gru_mma_split_kernel,
                         cudaFuncAttributeMaxDynamicSharedMemorySize, (int)smemBytes);

    gru_mma_split_kernel<<<UNITS * 2, NT, smemBytes>>>(
        x, h, Wir, bir, Whr, bhr, Wiz, biz, Whz, bhz, Win, bin, Whn, bhn, out);
}

// round 15
// speedup vs baseline: 1.2097x; 1.2097x over previous
#include <cuda_runtime.h>
#include <cstdint>

#define UNITS   512
#define NBATCH  512
#define DIM     64
#define MT      64            // batch rows per tile
#define NTILES  (NBATCH / MT) // 8
#define NT      512
#define CH      32            // output cols per CTA (2 CTAs per unit)
#define LD      68            // stride: bank(4g+t) all-distinct for fragment LDS
#define WHSZ    (CH * LD)     // 2176 floats per halved weight matrix

// ---- smem float offsets (total 22016 floats = 88,064 B -> 2 CTAs/SM) ----
#define SW_OFF  0                     // 6*WHSZ tf32 weights TRANSPOSED [o_local][k]
#define SX_OFF  (6 * WHSZ)            // MT*LD  raw x tile (single buffer)
#define SH_OFF  (SX_OFF + MT * LD)    // MT*LD  raw h tile (single buffer)
#define SB_OFF  (SH_OFF + MT * LD)    // 4*64 biases: r, z, in, hn (full width)
#define SMEM_FLOATS (SB_OFF + 256)

__device__ __forceinline__ uint32_t f2tf32(float x) {
    uint32_t u;
    asm volatile("cvt.rna.tf32.f32 %0, %1;" : "=r"(u) : "f"(x));
    return u;
}

__device__ __forceinline__ void mma8(float* d, const uint32_t* a, const uint32_t* b) {
    asm volatile(
        "mma.sync.aligned.m16n8k8.row.col.f32.tf32.tf32.f32 "
        "{%0,%1,%2,%3}, {%4,%5,%6,%7}, {%8,%9}, {%0,%1,%2,%3};"
        : "+f"(d[0]), "+f"(d[1]), "+f"(d[2]), "+f"(d[3])
        : "r"(a[0]), "r"(a[1]), "r"(a[2]), "r"(a[3]), "r"(b[0]), "r"(b[1]));
}

__device__ __forceinline__ float fast_sigmoid(float v) { return 1.f / (1.f + __expf(-v)); }
__device__ __forceinline__ float fast_tanh(float v)   { return 2.f / (1.f + __expf(-2.f * v)) - 1.f; }

// ---------------------------------------------------------------------------
// Grid = 1024: CTA (u, ch) computes unit u, output cols [ch*32, ch*32+32),
// all 512 batch rows as 8 tiles of 64. 512 threads = 16 warps: 4 row-groups
// (16 rows) x 4 col-groups (8 cols). 88 KB smem -> 2 CTAs/SM = 8 warps/SMSP;
// co-resident CTAs overlap each other's stage/barrier phases.
// ---------------------------------------------------------------------------
__global__ void __launch_bounds__(NT, 2)
gru_mma_2cta_kernel(const float* __restrict__ x,  const float* __restrict__ h,
                    const float* __restrict__ Wir, const float* __restrict__ bir,
                    const float* __restrict__ Whr, const float* __restrict__ bhr,
                    const float* __restrict__ Wiz, const float* __restrict__ biz,
                    const float* __restrict__ Whz, const float* __restrict__ bhz,
                    const float* __restrict__ Win, const float* __restrict__ bin,
                    const float* __restrict__ Whn, const float* __restrict__ bhn,
                    float* __restrict__ out) {
    extern __shared__ float smem[];

    const int u      = blockIdx.x >> 1;
    const int chBase = (blockIdx.x & 1) * CH;   // global col offset of this CTA
    const int tid  = threadIdx.x;
    const int lane = tid & 31;
    const int wid  = tid >> 5;
    const int g    = lane >> 2;            // mma groupID (0..7)
    const int t    = lane & 3;             // thread-in-group
    const int rowBase = (wid & 3) << 4;    // 4 row-warps x 16 rows = 64
    const int colBase = (wid >> 2) << 3;   // 4 col-warps x 8 cols  = 32 (local)

    const uint32_t sx_u32 = (uint32_t)__cvta_generic_to_shared(smem + SX_OFF);
    const uint32_t sh_u32 = (uint32_t)__cvta_generic_to_shared(smem + SH_OFF);

    // prefetch tile 0 (overlaps the weight prologue below)
    {
#pragma unroll
        for (int it = 0; it < 2; it++) {
            int cidx = tid + it * NT;
            int r  = cidx >> 4;
            int c4 = (cidx & 15) * 4;
            size_t ga = ((size_t)r * UNITS + u) * DIM + c4;
            uint32_t off = (uint32_t)(r * LD + c4) * 4;
            asm volatile("cp.async.cg.shared.global [%0], [%1], 16;"
                         :: "r"(sx_u32 + off), "l"(x + ga));
            asm volatile("cp.async.cg.shared.global [%0], [%1], 16;"
                         :: "r"(sh_u32 + off), "l"(h + ga));
        }
        asm volatile("cp.async.commit_group;");
    }

    // ---- stage this CTA's column-half of 6 weight matrices, TRANSPOSED ----
    {
        const float* wsrc[6] = {Wir, Whr, Wiz, Whz, Win, Whn};
        const size_t wOff = (size_t)u * DIM * DIM + chBase;
#pragma unroll
        for (int gg = 0; gg < 6; gg++) {
            const float* wp = wsrc[gg] + wOff;
            float* dst = smem + SW_OFF + gg * WHSZ;
            {
                int i  = tid;               // DIM*CH/4 = 512 = NT: one pass
                int k  = i >> 3;
                int o4 = (i & 7) * 4;
                float4 v = *reinterpret_cast<const float4*>(wp + k * DIM + o4);
                dst[(o4 + 0) * LD + k] = __uint_as_float(f2tf32(v.x));
                dst[(o4 + 1) * LD + k] = __uint_as_float(f2tf32(v.y));
                dst[(o4 + 2) * LD + k] = __uint_as_float(f2tf32(v.z));
                dst[(o4 + 3) * LD + k] = __uint_as_float(f2tf32(v.w));
            }
        }
        if (tid < DIM) {
            const size_t bo = (size_t)u * DIM + tid;
            smem[SB_OFF + tid]           = bir[bo] + bhr[bo];
            smem[SB_OFF + 64 + tid]      = biz[bo] + bhz[bo];
            smem[SB_OFF + 128 + tid]     = bin[bo];
            smem[SB_OFF + 192 + tid]     = bhn[bo];
        }
    }

    const float* sW  = smem + SW_OFF;
    const float* sXt = smem + SX_OFF;
    const float* sHt = smem + SH_OFF;

    for (int tile = 0; tile < NTILES; tile++) {
        const int b0 = tile * MT;

        asm volatile("cp.async.wait_group 0;" ::: "memory");
        __syncthreads();

        // ---- fused 6-GEMM k-loop, warp tile 16x8 (cvt-at-load, proven) ----
        float accR[4], accZ[4], accN[4], accH[4];
#pragma unroll
        for (int i = 0; i < 4; i++) {
            accR[i] = 0.f; accZ[i] = 0.f; accN[i] = 0.f; accH[i] = 0.f;
        }

#pragma unroll
        for (int ks = 0; ks < 8; ks++) {
            const int k0 = ks * 8;
            uint32_t ax[4], ah[4];
            {
                const float* ap = sXt + (rowBase + g) * LD + k0 + t;
                ax[0] = f2tf32(ap[0]);
                ax[1] = f2tf32(ap[8 * LD]);
                ax[2] = f2tf32(ap[4]);
                ax[3] = f2tf32(ap[8 * LD + 4]);
                const float* hp = sHt + (rowBase + g) * LD + k0 + t;
                ah[0] = f2tf32(hp[0]);
                ah[1] = f2tf32(hp[8 * LD]);
                ah[2] = f2tf32(hp[4]);
                ah[3] = f2tf32(hp[8 * LD + 4]);
            }
            const float* bp = sW + (colBase + g) * LD + k0 + t;  // bank 4g+t: clean
            uint32_t b[2];
            b[0] = __float_as_uint(bp[0 * WHSZ]); b[1] = __float_as_uint(bp[0 * WHSZ + 4]);
            mma8(accR, ax, b);                                   // x@Wir
            b[0] = __float_as_uint(bp[1 * WHSZ]); b[1] = __float_as_uint(bp[1 * WHSZ + 4]);
            mma8(accR, ah, b);                                   // h@Whr
            b[0] = __float_as_uint(bp[2 * WHSZ]); b[1] = __float_as_uint(bp[2 * WHSZ + 4]);
            mma8(accZ, ax, b);                                   // x@Wiz
            b[0] = __float_as_uint(bp[3 * WHSZ]); b[1] = __float_as_uint(bp[3 * WHSZ + 4]);
            mma8(accZ, ah, b);                                   // h@Whz
            b[0] = __float_as_uint(bp[4 * WHSZ]); b[1] = __float_as_uint(bp[4 * WHSZ + 4]);
            mma8(accN, ax, b);                                   // x@Win
            b[0] = __float_as_uint(bp[5 * WHSZ]); b[1] = __float_as_uint(bp[5 * WHSZ + 4]);
            mma8(accH, ah, b);                                   // h@Whn
        }

        // ---- fused GRU epilogue, direct float2 gmem stores ----
        const int colg = chBase + colBase + 2 * t;   // global output col
#pragma unroll
        for (int half = 0; half < 2; half++) {
            const int row = rowBase + g + half * 8;
            float2 hv = *reinterpret_cast<const float2*>(sHt + row * LD + colg);
            float2 res;
            {
                const int idx = half * 2;
                float r_ = fast_sigmoid(accR[idx] + smem[SB_OFF + colg]);
                float z_ = fast_sigmoid(accZ[idx] + smem[SB_OFF + 64 + colg]);
                float n_ = fast_tanh(accN[idx] + smem[SB_OFF + 128 + colg] +
                                     r_ * (accH[idx] + smem[SB_OFF + 192 + colg]));
                res.x = (1.f - z_) * n_ + z_ * hv.x;
            }
            {
                const int idx = half * 2 + 1;
                float r_ = fast_sigmoid(accR[idx] + smem[SB_OFF + colg + 1]);
                float z_ = fast_sigmoid(accZ[idx] + smem[SB_OFF + 64 + colg + 1]);
                float n_ = fast_tanh(accN[idx] + smem[SB_OFF + 128 + colg + 1] +
                                     r_ * (accH[idx] + smem[SB_OFF + 192 + colg + 1]));
                res.y = (1.f - z_) * n_ + z_ * hv.y;
            }
            size_t ga = ((size_t)(b0 + row) * UNITS + u) * DIM + colg;
            *reinterpret_cast<float2*>(out + ga) = res;
        }

        __syncthreads();   // all reads of sXt/sHt done before restaging

        if (tile + 1 < NTILES) {
            const int b0n = b0 + MT;
#pragma unroll
            for (int it = 0; it < 2; it++) {
                int cidx = tid + it * NT;
                int r  = cidx >> 4;
                int c4 = (cidx & 15) * 4;
                size_t ga = ((size_t)(b0n + r) * UNITS + u) * DIM + c4;
                uint32_t off = (uint32_t)(r * LD + c4) * 4;
                asm volatile("cp.async.cg.shared.global [%0], [%1], 16;"
                             :: "r"(sx_u32 + off), "l"(x + ga));
                asm volatile("cp.async.cg.shared.global [%0], [%1], 16;"
                             :: "r"(sh_u32 + off), "l"(h + ga));
            }
            asm volatile("cp.async.commit_group;");
        }
    }
}

// ---------------------------------------------------------------------------
extern "C" void kernel_launch(void* const* d_in, const int* in_sizes, int n_in,
                              void* d_out, int out_size) {
    (void)in_sizes; (void)n_in; (void)out_size;
    const float* x   = (const float*)d_in[0];
    const float* h   = (const float*)d_in[1];
    const float* Wir = (const float*)d_in[2];
    const float* bir = (const float*)d_in[3];
    const float* Whr = (const float*)d_in[4];
    const float* bhr = (const float*)d_in[5];
    const float* Wiz = (const float*)d_in[6];
    const float* biz = (const float*)d_in[7];
    const float* Whz = (const float*)d_in[8];
    const float* bhz = (const float*)d_in[9];
    const float* Win = (const float*)d_in[10];
    const float* bin = (const float*)d_in[11];
    const float* Whn = (const float*)d_in[12];
    const float* bhn = (const float*)d_in[13];
    float* out = (float*)d_out;

    const size_t smemBytes = (size_t)SMEM_FLOATS * sizeof(float);
    cudaFuncSetAttribute(gru_mma_2cta_kernel,
                         cudaFuncAttributeMaxDynamicSharedMemorySize, (int)smemBytes);

    gru_mma_2cta_kernel<<<UNITS * 2, NT, smemBytes>>>(
        x, h, Wir, bir, Whr, bhr, Wiz, biz, Whz, bhz, Win, bin, Whn, bhn, out);
}

// round 17
// speedup vs baseline: 1.2254x; 1.0130x over previous
#include <cuda_runtime.h>
#include <cstdint>

#define UNITS   512
#define NBATCH  512
#define DIM     64
#define MT      64            // batch rows per tile
#define NTILES  (NBATCH / MT) // 8
#define NT      512
#define CH      32            // output cols per CTA (2 CTAs per unit)
#define LD      68            // stride: bank(4g+t) all-distinct for fragment LDS
#define WHSZ    (CH * LD)     // 2176 floats per halved weight matrix

// ---- smem float offsets (total 22016 floats = 88,064 B -> 2 CTAs/SM) ----
#define SW_OFF  0                     // 6*WHSZ tf32 weights TRANSPOSED [o_local][k]
#define SX_OFF  (6 * WHSZ)            // MT*LD  raw x tile (single buffer)
#define SH_OFF  (SX_OFF + MT * LD)    // MT*LD  raw h tile (single buffer)
#define SB_OFF  (SH_OFF + MT * LD)    // 4*64 biases: r, z, in, hn (full width)
#define SMEM_FLOATS (SB_OFF + 256)

__device__ __forceinline__ uint32_t f2tf32(float x) {
    uint32_t u;
    asm volatile("cvt.rna.tf32.f32 %0, %1;" : "=r"(u) : "f"(x));
    return u;
}

__device__ __forceinline__ void mma8(float* d, const uint32_t* a, const uint32_t* b) {
    asm volatile(
        "mma.sync.aligned.m16n8k8.row.col.f32.tf32.tf32.f32 "
        "{%0,%1,%2,%3}, {%4,%5,%6,%7}, {%8,%9}, {%0,%1,%2,%3};"
        : "+f"(d[0]), "+f"(d[1]), "+f"(d[2]), "+f"(d[3])
        : "r"(a[0]), "r"(a[1]), "r"(a[2]), "r"(a[3]), "r"(b[0]), "r"(b[1]));
}

__device__ __forceinline__ float fast_sigmoid(float v) { return 1.f / (1.f + __expf(-v)); }
__device__ __forceinline__ float fast_tanh(float v)   { return 2.f / (1.f + __expf(-2.f * v)) - 1.f; }

// ---------------------------------------------------------------------------
// Identical to the passing R15 kernel except ONE change: activation fragments
// are fed to HMMA as raw fp32 bits (HW RZ-truncation to tf32) instead of
// cvt.rna per element -> 16 fewer dependent instructions per warp per k-step.
// Grid = 1024: CTA (u, ch) computes unit u, output cols [ch*32, ch*32+32),
// 8 tiles of 64 rows. 88 KB smem -> 2 CTAs/SM = 8 warps/SMSP.
// ---------------------------------------------------------------------------
__global__ void __launch_bounds__(NT, 2)
gru_mma_rz_kernel(const float* __restrict__ x,  const float* __restrict__ h,
                  const float* __restrict__ Wir, const float* __restrict__ bir,
                  const float* __restrict__ Whr, const float* __restrict__ bhr,
                  const float* __restrict__ Wiz, const float* __restrict__ biz,
                  const float* __restrict__ Whz, const float* __restrict__ bhz,
                  const float* __restrict__ Win, const float* __restrict__ bin,
                  const float* __restrict__ Whn, const float* __restrict__ bhn,
                  float* __restrict__ out) {
    extern __shared__ float smem[];

    const int u      = blockIdx.x >> 1;
    const int chBase = (blockIdx.x & 1) * CH;   // global col offset of this CTA
    const int tid  = threadIdx.x;
    const int lane = tid & 31;
    const int wid  = tid >> 5;
    const int g    = lane >> 2;            // mma groupID (0..7)
    const int t    = lane & 3;             // thread-in-group
    const int rowBase = (wid & 3) << 4;    // 4 row-warps x 16 rows = 64
    const int colBase = (wid >> 2) << 3;   // 4 col-warps x 8 cols  = 32 (local)

    const uint32_t sx_u32 = (uint32_t)__cvta_generic_to_shared(smem + SX_OFF);
    const uint32_t sh_u32 = (uint32_t)__cvta_generic_to_shared(smem + SH_OFF);

    // prefetch tile 0 (overlaps the weight prologue below)
    {
#pragma unroll
        for (int it = 0; it < 2; it++) {
            int cidx = tid + it * NT;
            int r  = cidx >> 4;
            int c4 = (cidx & 15) * 4;
            size_t ga = ((size_t)r * UNITS + u) * DIM + c4;
            uint32_t off = (uint32_t)(r * LD + c4) * 4;
            asm volatile("cp.async.cg.shared.global [%0], [%1], 16;"
                         :: "r"(sx_u32 + off), "l"(x + ga));
            asm volatile("cp.async.cg.shared.global [%0], [%1], 16;"
                         :: "r"(sh_u32 + off), "l"(h + ga));
        }
        asm volatile("cp.async.commit_group;");
    }

    // ---- stage this CTA's column-half of 6 weight matrices, TRANSPOSED ----
    {
        const float* wsrc[6] = {Wir, Whr, Wiz, Whz, Win, Whn};
        const size_t wOff = (size_t)u * DIM * DIM + chBase;
#pragma unroll
        for (int gg = 0; gg < 6; gg++) {
            const float* wp = wsrc[gg] + wOff;
            float* dst = smem + SW_OFF + gg * WHSZ;
            {
                int i  = tid;               // DIM*CH/4 = 512 = NT: one pass
                int k  = i >> 3;
                int o4 = (i & 7) * 4;
                float4 v = *reinterpret_cast<const float4*>(wp + k * DIM + o4);
                dst[(o4 + 0) * LD + k] = __uint_as_float(f2tf32(v.x));
                dst[(o4 + 1) * LD + k] = __uint_as_float(f2tf32(v.y));
                dst[(o4 + 2) * LD + k] = __uint_as_float(f2tf32(v.z));
                dst[(o4 + 3) * LD + k] = __uint_as_float(f2tf32(v.w));
            }
        }
        if (tid < DIM) {
            const size_t bo = (size_t)u * DIM + tid;
            smem[SB_OFF + tid]           = bir[bo] + bhr[bo];
            smem[SB_OFF + 64 + tid]      = biz[bo] + bhz[bo];
            smem[SB_OFF + 128 + tid]     = bin[bo];
            smem[SB_OFF + 192 + tid]     = bhn[bo];
        }
    }

    const float* sW  = smem + SW_OFF;
    const float* sXt = smem + SX_OFF;
    const float* sHt = smem + SH_OFF;

    for (int tile = 0; tile < NTILES; tile++) {
        const int b0 = tile * MT;

        asm volatile("cp.async.wait_group 0;" ::: "memory");
        __syncthreads();

        // ---- fused 6-GEMM k-loop; raw-bit (RZ-tf32) activation fragments ----
        float accR[4], accZ[4], accN[4], accH[4];
#pragma unroll
        for (int i = 0; i < 4; i++) {
            accR[i] = 0.f; accZ[i] = 0.f; accN[i] = 0.f; accH[i] = 0.f;
        }

#pragma unroll
        for (int ks = 0; ks < 8; ks++) {
            const int k0 = ks * 8;
            uint32_t ax[4], ah[4];
            {
                const float* ap = sXt + (rowBase + g) * LD + k0 + t;
                ax[0] = __float_as_uint(ap[0]);
                ax[1] = __float_as_uint(ap[8 * LD]);
                ax[2] = __float_as_uint(ap[4]);
                ax[3] = __float_as_uint(ap[8 * LD + 4]);
                const float* hp = sHt + (rowBase + g) * LD + k0 + t;
                ah[0] = __float_as_uint(hp[0]);
                ah[1] = __float_as_uint(hp[8 * LD]);
                ah[2] = __float_as_uint(hp[4]);
                ah[3] = __float_as_uint(hp[8 * LD + 4]);
            }
            const float* bp = sW + (colBase + g) * LD + k0 + t;  // bank 4g+t: clean
            uint32_t b[2];
            b[0] = __float_as_uint(bp[0 * WHSZ]); b[1] = __float_as_uint(bp[0 * WHSZ + 4]);
            mma8(accR, ax, b);                                   // x@Wir
            b[0] = __float_as_uint(bp[1 * WHSZ]); b[1] = __float_as_uint(bp[1 * WHSZ + 4]);
            mma8(accR, ah, b);                                   // h@Whr
            b[0] = __float_as_uint(bp[2 * WHSZ]); b[1] = __float_as_uint(bp[2 * WHSZ + 4]);
            mma8(accZ, ax, b);                                   // x@Wiz
            b[0] = __float_as_uint(bp[3 * WHSZ]); b[1] = __float_as_uint(bp[3 * WHSZ + 4]);
            mma8(accZ, ah, b);                                   // h@Whz
            b[0] = __float_as_uint(bp[4 * WHSZ]); b[1] = __float_as_uint(bp[4 * WHSZ + 4]);
            mma8(accN, ax, b);                                   // x@Win
            b[0] = __float_as_uint(bp[5 * WHSZ]); b[1] = __float_as_uint(bp[5 * WHSZ + 4]);
            mma8(accH, ah, b);                                   // h@Whn
        }

        // ---- fused GRU epilogue, direct float2 gmem stores ----
        const int colg = chBase + colBase + 2 * t;   // global output col
#pragma unroll
        for (int half = 0; half < 2; half++) {
            const int row = rowBase + g + half * 8;
            float2 hv = *reinterpret_cast<const float2*>(sHt + row * LD + colg);
            float2 res;
            {
                const int idx = half * 2;
                float r_ = fast_sigmoid(accR[idx] + smem[SB_OFF + colg]);
                float z_ = fast_sigmoid(accZ[idx] + smem[SB_OFF + 64 + colg]);
                float n_ = fast_tanh(accN[idx] + smem[SB_OFF + 128 + colg] +
                                     r_ * (accH[idx] + smem[SB_OFF + 192 + colg]));
                res.x = (1.f - z_) * n_ + z_ * hv.x;
            }
            {
                const int idx = half * 2 + 1;
                float r_ = fast_sigmoid(accR[idx] + smem[SB_OFF + colg + 1]);
                float z_ = fast_sigmoid(accZ[idx] + smem[SB_OFF + 64 + colg + 1]);
                float n_ = fast_tanh(accN[idx] + smem[SB_OFF + 128 + colg + 1] +
                                     r_ * (accH[idx] + smem[SB_OFF + 192 + colg + 1]));
                res.y = (1.f - z_) * n_ + z_ * hv.y;
            }
            size_t ga = ((size_t)(b0 + row) * UNITS + u) * DIM + colg;
            *reinterpret_cast<float2*>(out + ga) = res;
        }

        __syncthreads();   // all reads of sXt/sHt done before restaging

        if (tile + 1 < NTILES) {
            const int b0n = b0 + MT;
#pragma unroll
            for (int it = 0; it < 2; it++) {
                int cidx = tid + it * NT;
                int r  = cidx >> 4;
                int c4 = (cidx & 15) * 4;
                size_t ga = ((size_t)(b0n + r) * UNITS + u) * DIM + c4;
                uint32_t off = (uint32_t)(r * LD + c4) * 4;
                asm volatile("cp.async.cg.shared.global [%0], [%1], 16;"
                             :: "r"(sx_u32 + off), "l"(x + ga));
                asm volatile("cp.async.cg.shared.global [%0], [%1], 16;"
                             :: "r"(sh_u32 + off), "l"(h + ga));
            }
            asm volatile("cp.async.commit_group;");
        }
    }
}

// ---------------------------------------------------------------------------
extern "C" void kernel_launch(void* const* d_in, const int* in_sizes, int n_in,
                              void* d_out, int out_size) {
    (void)in_sizes; (void)n_in; (void)out_size;
    const float* x   = (const float*)d_in[0];
    const float* h   = (const float*)d_in[1];
    const float* Wir = (const float*)d_in[2];
    const float* bir = (const float*)d_in[3];
    const float* Whr = (const float*)d_in[4];
    const float* bhr = (const float*)d_in[5];
    const float* Wiz = (const float*)d_in[6];
    const float* biz = (const float*)d_in[7];
    const float* Whz = (const float*)d_in[8];
    const float* bhz = (const float*)d_in[9];
    const float* Win = (const float*)d_in[10];
    const float* bin = (const float*)d_in[11];
    const float* Whn = (const float*)d_in[12];
    const float* bhn = (const float*)d_in[13];
    float* out = (float*)d_out;

    const size_t smemBytes = (size_t)SMEM_FLOATS * sizeof(float);
    cudaFuncSetAttribute(gru_mma_rz_kernel,
                         cudaFuncAttributeMaxDynamicSharedMemorySize, (int)smemBytes);

    gru_mma_rz_kernel<<<UNITS * 2, NT, smemBytes>>>(
        x, h, Wir, bir, Whr, bhr, Wiz, biz, Whz, bhz, Win, bin, Whn, bhn, out);
}